// round 8
// baseline (speedup 1.0000x reference)
#include <cuda_runtime.h>

#define BB   32
#define D3D  256
#define D2D  768
#define DT   3072
#define PP   3072
#define SS   256
#define TT   512
#define SEQ  256
#define XK   (PP*3)     // 9216

#define KS2  192        // k-split for u (p-chunks of 16)
#define SC2  8          // 2D s-splits (chunk 32)
#define TS   32         // text splits per batch (chunk 16)
#define KS7  72         // fused GEMM global splits (k-chunk 128)
#define RS7  132        // ws row stride (floats)

// ---- scratch (static device memory; no allocation) ----
__device__ float g_f3p[BB*PP];
__device__ float g_upart[KS2*BB*D2D];
__device__ float g_u[BB*D2D];
__device__ float g_m2[BB*SC2];
__device__ float g_z2[BB*SC2];
__device__ float g_v2[BB*SC2*D2D];
__device__ float g_g[BB*D2D];
__device__ float g_p2d[BB*PP];
__device__ float g_mpart[BB*TS];
__device__ float g_zpart[BB*TS];
__device__ float g_vpart[BB*TS*PP];
__device__ float g_ptext[BB*PP];
__device__ float g_fpart[KS7*BB*PP];
__device__ float g_fvec[BB*PP];

__device__ __forceinline__ float warp_sum(float v){
    #pragma unroll
    for (int o = 16; o; o >>= 1) v += __shfl_xor_sync(0xffffffffu, v, o);
    return v;
}

__device__ __forceinline__ void ffma2(unsigned long long& d, unsigned long long a,
                                      unsigned long long b){
    asm("fma.rn.f32x2 %0, %1, %2, %0;" : "+l"(d) : "l"(a), "l"(b));
}

__device__ __forceinline__ unsigned long long dup2(float x){
    unsigned long long r;
    unsigned int u = __float_as_uint(x);
    asm("mov.b64 %0, {%1, %1};" : "=l"(r) : "r"(u));
    return r;
}

__device__ __forceinline__ float dot4(float4 a, float4 b){
    return a.x*b.x + a.y*b.y + a.z*b.z + a.w*b.w;
}

// ---- K1: f3p = feat_3d @ W3d^T + b3d ----
__global__ void k1_f3p(const float* __restrict__ f3, const float* __restrict__ W3,
                       const float* __restrict__ b3){
    int bg = blockIdx.x / 96, pt = blockIdx.x % 96;
    int p0 = pt * 32;
    __shared__ float fs[8*D3D];
    int tid = threadIdx.x, w = tid >> 5, lane = tid & 31;
    #pragma unroll
    for (int e = tid; e < 8*D3D; e += 256) fs[e] = f3[bg*8*D3D + e];
    __syncthreads();
    const float4* fs4 = (const float4*)fs;
    for (int i = 0; i < 4; i++){
        int p = p0 + w*4 + i;
        const float4* row = (const float4*)(W3 + p*D3D);
        float4 a0 = row[lane], a1 = row[lane+32];
        float acc[8];
        #pragma unroll
        for (int bb = 0; bb < 8; bb++){
            float4 c0 = fs4[bb*64 + lane], c1 = fs4[bb*64 + lane + 32];
            acc[bb] = dot4(a0,c0) + dot4(a1,c1);
        }
        #pragma unroll
        for (int bb = 0; bb < 8; bb++){
            float s = warp_sum(acc[bb]);
            if (!lane) g_f3p[(bg*8 + bb)*PP + p] = s + b3[p];
        }
    }
}

// ---- K2: u partials (p-chunks of 16) ----
__global__ void k2_u(const float* __restrict__ W2){
    int dt = blockIdx.x % 3, ks = blockIdx.x / 3;
    int tid = threadIdx.x;
    int d = dt*256 + tid;
    int pbase = ks * 16;
    __shared__ float fs[BB*16];
    for (int e = tid; e < BB*16; e += 256){
        int bb = e >> 4, pp = e & 15;
        fs[e] = g_f3p[bb*PP + pbase + pp];
    }
    __syncthreads();
    float acc[BB];
    #pragma unroll
    for (int bb = 0; bb < BB; bb++) acc[bb] = 0.f;
    const float4* fs4 = (const float4*)fs;
    #pragma unroll
    for (int pp = 0; pp < 16; pp += 4){
        float w0 = W2[(pbase+pp+0)*D2D + d];
        float w1 = W2[(pbase+pp+1)*D2D + d];
        float w2 = W2[(pbase+pp+2)*D2D + d];
        float w3 = W2[(pbase+pp+3)*D2D + d];
        #pragma unroll
        for (int bb = 0; bb < BB; bb++){
            float4 f = fs4[bb*4 + (pp >> 2)];
            acc[bb] += f.x*w0 + f.y*w1 + f.z*w2 + f.w*w3;
        }
    }
    #pragma unroll
    for (int bb = 0; bb < BB; bb++)
        g_upart[(size_t)(ks*BB + bb)*D2D + d] = acc[bb];
}

// ---- K2b: reduce partials -> g_u ----
__global__ void k_ured(void){
    int e = blockIdx.x * 256 + threadIdx.x;
    const float4* up = (const float4*)g_upart;
    float4 s = {0,0,0,0};
    #pragma unroll 8
    for (int ks = 0; ks < KS2; ks++){
        float4 v = up[(size_t)ks*(BB*D2D/4) + e];
        s.x += v.x; s.y += v.y; s.z += v.z; s.w += v.w;
    }
    ((float4*)g_u)[e] = s;
}

// ---- K3a: 2D pooling, online softmax, batch-8 rows per sync round ----
__global__ void __launch_bounds__(192) k3a_s2d(const float* __restrict__ f2d){
    __shared__ float red[8][6];
    __shared__ float sbc[8];
    int b = blockIdx.x >> 3, cs = blockIdx.x & 7;
    int s0 = cs * 32;
    int tid = threadIdx.x, w = tid >> 5, lane = tid & 31;
    float4 q = ((const float4*)(g_u + b*D2D))[tid];
    const float4* base = (const float4*)(f2d + ((size_t)(b*SS + s0))*D2D);
    float m = -1e30f, z = 0.f;
    float4 acc = {0,0,0,0};
    for (int tb = 0; tb < 4; tb++){
        float4 r[8];
        #pragma unroll
        for (int j = 0; j < 8; j++) r[j] = base[(tb*8 + j)*192 + tid];
        #pragma unroll
        for (int j = 0; j < 8; j++){
            float p = dot4(r[j], q);
            p = warp_sum(p);
            if (!lane) red[j][w] = p;
        }
        __syncthreads();
        if (tid < 8){
            float s = 0.f;
            #pragma unroll
            for (int i = 0; i < 6; i++) s += red[tid][i];
            sbc[tid] = s;
        }
        __syncthreads();
        #pragma unroll
        for (int j = 0; j < 8; j++){
            float s = sbc[j];
            float mn = fmaxf(m, s);
            float cf = expf(m - mn), wv = expf(s - mn);
            z = z*cf + wv;
            acc.x = acc.x*cf + wv*r[j].x; acc.y = acc.y*cf + wv*r[j].y;
            acc.z = acc.z*cf + wv*r[j].z; acc.w = acc.w*cf + wv*r[j].w;
            m = mn;
        }
        __syncthreads();
    }
    ((float4*)g_v2)[(b*SC2 + cs)*(D2D/4) + tid] = acc;
    if (tid == 0){ g_m2[b*SC2 + cs] = m; g_z2[b*SC2 + cs] = z; }
}

// ---- K3b: combine 2D partials -> g_g ----
__global__ void k3b_comb(void){
    int b = blockIdx.x, tid = threadIdx.x;
    float mv[SC2], co[SC2];
    float m = -1e30f;
    #pragma unroll
    for (int i = 0; i < SC2; i++){ mv[i] = g_m2[b*SC2 + i]; m = fmaxf(m, mv[i]); }
    float zt = 0.f;
    #pragma unroll
    for (int i = 0; i < SC2; i++){ co[i] = expf(mv[i] - m); zt += co[i] * g_z2[b*SC2 + i]; }
    float inv = 1.f / zt;
    if (tid < 192){
        float4 s = {0,0,0,0};
        #pragma unroll
        for (int i = 0; i < SC2; i++){
            float4 v = ((const float4*)g_v2)[(b*SC2 + i)*(D2D/4) + tid];
            s.x += co[i]*v.x; s.y += co[i]*v.y; s.z += co[i]*v.z; s.w += co[i]*v.w;
        }
        s.x *= inv; s.y *= inv; s.z *= inv; s.w *= inv;
        ((float4*)g_g)[b*(D2D/4) + tid] = s;
    }
}

// ---- K4: pooled_2d = g @ W2^T + b2d ----
__global__ void k4_p2d(const float* __restrict__ W2, const float* __restrict__ b2){
    int bg = blockIdx.x / 96, pt = blockIdx.x % 96;
    int p0 = pt * 32;
    __shared__ float gs[8*D2D];
    int tid = threadIdx.x, w = tid >> 5, lane = tid & 31;
    #pragma unroll
    for (int e = tid; e < 8*D2D; e += 256) gs[e] = g_g[bg*8*D2D + e];
    __syncthreads();
    const float4* gs4 = (const float4*)gs;
    for (int i = 0; i < 4; i++){
        int p = p0 + w*4 + i;
        const float4* row = (const float4*)(W2 + p*D2D);
        float4 a[6];
        #pragma unroll
        for (int j = 0; j < 6; j++) a[j] = row[lane + 32*j];
        float acc[8];
        #pragma unroll
        for (int bb = 0; bb < 8; bb++){
            float s = 0.f;
            #pragma unroll
            for (int j = 0; j < 6; j++) s += dot4(a[j], gs4[bb*192 + lane + 32*j]);
            acc[bb] = s;
        }
        #pragma unroll
        for (int bb = 0; bb < 8; bb++){
            float s = warp_sum(acc[bb]);
            if (!lane) g_p2d[(bg*8 + bb)*PP + p] = s + b2[p];
        }
    }
}

// ---- K5: text pooling, online softmax, batch-4 rows per sync round ----
__global__ void __launch_bounds__(256) k5_text(const float* __restrict__ ft){
    __shared__ float red[4][8];
    __shared__ float sbc[4];
    int b = blockIdx.x >> 5, ks = blockIdx.x & 31;
    int t0 = ks * 16;
    int tid = threadIdx.x, w = tid >> 5, lane = tid & 31;
    const float4* qg = (const float4*)(g_f3p + b*PP);
    float4 q0 = qg[tid], q1 = qg[tid+256], q2 = qg[tid+512];
    const float4* base = (const float4*)(ft + ((size_t)(b*TT + t0))*DT);
    float m = -1e30f, z = 0.f;
    float4 a0 = {0,0,0,0}, a1 = {0,0,0,0}, a2 = {0,0,0,0};
    for (int tb = 0; tb < 4; tb++){
        float4 r[4][3];
        #pragma unroll
        for (int j = 0; j < 4; j++){
            const float4* rb = base + (tb*4 + j)*768;
            r[j][0] = rb[tid]; r[j][1] = rb[tid+256]; r[j][2] = rb[tid+512];
        }
        #pragma unroll
        for (int j = 0; j < 4; j++){
            float p = dot4(r[j][0],q0) + dot4(r[j][1],q1) + dot4(r[j][2],q2);
            p = warp_sum(p);
            if (!lane) red[j][w] = p;
        }
        __syncthreads();
        if (tid < 4){
            float s = 0.f;
            #pragma unroll
            for (int i = 0; i < 8; i++) s += red[tid][i];
            sbc[tid] = s;
        }
        __syncthreads();
        #pragma unroll
        for (int j = 0; j < 4; j++){
            float s = sbc[j];
            float mn = fmaxf(m, s);
            float cf = expf(m - mn), wv = expf(s - mn);
            z = z*cf + wv;
            a0.x = a0.x*cf + wv*r[j][0].x; a0.y = a0.y*cf + wv*r[j][0].y;
            a0.z = a0.z*cf + wv*r[j][0].z; a0.w = a0.w*cf + wv*r[j][0].w;
            a1.x = a1.x*cf + wv*r[j][1].x; a1.y = a1.y*cf + wv*r[j][1].y;
            a1.z = a1.z*cf + wv*r[j][1].z; a1.w = a1.w*cf + wv*r[j][1].w;
            a2.x = a2.x*cf + wv*r[j][2].x; a2.y = a2.y*cf + wv*r[j][2].y;
            a2.z = a2.z*cf + wv*r[j][2].z; a2.w = a2.w*cf + wv*r[j][2].w;
            m = mn;
        }
        __syncthreads();
    }
    float4* vp4 = (float4*)g_vpart;
    size_t vb = (size_t)(b*TS + ks) * (PP/4);
    vp4[vb + tid] = a0; vp4[vb + tid + 256] = a1; vp4[vb + tid + 512] = a2;
    if (tid == 0){ g_mpart[b*TS + ks] = m; g_zpart[b*TS + ks] = z; }
}

// ---- K6: combine text partials ----
__global__ void __launch_bounds__(64) k6_comb(void){
    int b = blockIdx.x / 12, ct = blockIdx.x % 12;
    int tid = threadIdx.x;
    __shared__ float ms[TS], zp[TS];
    if (tid < TS){ ms[tid] = g_mpart[b*TS + tid]; zp[tid] = g_zpart[b*TS + tid]; }
    __syncthreads();
    float m = -1e30f;
    #pragma unroll
    for (int i = 0; i < TS; i++) m = fmaxf(m, ms[i]);
    float co[TS];
    float zt = 0.f;
    #pragma unroll
    for (int i = 0; i < TS; i++){ co[i] = expf(ms[i] - m); zt += co[i] * zp[i]; }
    float inv = 1.f / zt;
    int p4 = ct*64 + tid;
    float4 s = {0,0,0,0};
    #pragma unroll 4
    for (int i = 0; i < TS; i++){
        float c = co[i];
        float4 v = ((const float4*)g_vpart)[(size_t)(b*TS + i)*(PP/4) + p4];
        s.x += c*v.x; s.y += c*v.y; s.z += c*v.z; s.w += c*v.w;
    }
    s.x *= inv; s.y *= inv; s.z *= inv; s.w *= inv;
    ((float4*)g_ptext)[b*(PP/4) + p4] = s;
}

// ---- K7: fused GEMM partials, p-paired FFMA2, one k-region ----
// grid 576 = 24 pt x 24 kst; block 256 = 8 bg x 32 pg; tile/thread 4b x 4p
__global__ void __launch_bounds__(256) k7_fused(const float* __restrict__ Wf,
                                                const float* __restrict__ xsrc,
                                                int kbase){
    int pt = blockIdx.x % 24, kst = blockIdx.x / 24;
    int p0 = pt * 128;
    int koff = kst * 128;
    int kglob = kbase + koff;
    int ks = kbase/128 + kst;
    __shared__ float ws[16*RS7];   // [k][p], conflict-free (16B lane stride)
    __shared__ float xs[16*36];    // [k][b]
    int tid = threadIdx.x;
    int bg = tid >> 5, pg = tid & 31;
    int b0 = bg * 4, pp0 = pg * 4;
    unsigned long long acc[4][2];
    #pragma unroll
    for (int i = 0; i < 4; i++){ acc[i][0] = 0ull; acc[i][1] = 0ull; }

    for (int kt = 0; kt < 128; kt += 16){
        // stage ws[k][p]: 16k x 128p (256 threads, 2 rows each)
        {
            int c = tid & 3, r0 = tid >> 2;   // r0: 0..63
            #pragma unroll
            for (int i = 0; i < 2; i++){
                int r = r0 + i*64;
                float4 v = *(const float4*)&Wf[(size_t)(p0 + r)*XK + kglob + kt + c*4];
                ws[(c*4+0)*RS7 + r] = v.x;
                ws[(c*4+1)*RS7 + r] = v.y;
                ws[(c*4+2)*RS7 + r] = v.z;
                ws[(c*4+3)*RS7 + r] = v.w;
            }
        }
        // stage xs[k][b]: 16k x 32b (first 128 threads)
        if (tid < 128){
            int bb = tid >> 2, kq = (tid & 3) * 4;
            float4 v = *(const float4*)&xsrc[bb*PP + koff + kt + kq];
            xs[(kq+0)*36 + bb] = v.x;
            xs[(kq+1)*36 + bb] = v.y;
            xs[(kq+2)*36 + bb] = v.z;
            xs[(kq+3)*36 + bb] = v.w;
        }
        __syncthreads();
        #pragma unroll
        for (int k = 0; k < 16; k++){
            float4 xv = *(const float4*)&xs[k*36 + b0];   // broadcast
            unsigned long long xd[4];
            xd[0] = dup2(xv.x); xd[1] = dup2(xv.y);
            xd[2] = dup2(xv.z); xd[3] = dup2(xv.w);
            ulonglong2 wp = *(const ulonglong2*)&ws[k*RS7 + pp0];
            #pragma unroll
            for (int i = 0; i < 4; i++){
                ffma2(acc[i][0], xd[i], wp.x);
                ffma2(acc[i][1], xd[i], wp.y);
            }
        }
        __syncthreads();
    }
    #pragma unroll
    for (int i = 0; i < 4; i++){
        int b = b0 + i;
        ulonglong2 o = {acc[i][0], acc[i][1]};
        *(ulonglong2*)&g_fpart[(size_t)(ks*BB + b)*PP + p0 + pp0] = o;
    }
}

// ---- K8a: reduce fused partials + bias -> fvec ----
__global__ void k8a_red(const float* __restrict__ bf){
    int e = blockIdx.x * 256 + threadIdx.x;   // 24576 float4
    int b = e / (PP/4), p4 = e % (PP/4);
    float4 v = ((const float4*)bf)[p4];
    const float4* fp4 = (const float4*)g_fpart;
    #pragma unroll 8
    for (int ks = 0; ks < KS7; ks++){
        float4 a = fp4[(size_t)(ks*BB + b)*(PP/4) + p4];
        v.x += a.x; v.y += a.y; v.z += a.z; v.w += a.w;
    }
    ((float4*)g_fvec)[e] = v;
}

// ---- K8b: broadcast over SEQ ----
__global__ void k8b_out(float* __restrict__ out){
    int bx = blockIdx.x;            // 768 = 32 b x 24 (3 pt x 8 ss)
    int b = bx / 24;
    int rem = bx % 24;
    int pt = rem % 3, ss = rem / 3;
    int tid = threadIdx.x;
    int p4 = pt*256 + tid;
    float4 v = ((const float4*)g_fvec)[b*(PP/4) + p4];
    size_t base = ((size_t)b*SEQ + ss*32)*PP;
    float4* o4 = (float4*)(out + base);
    #pragma unroll 4
    for (int s = 0; s < 32; s++)
        o4[(size_t)s*(PP/4) + p4] = v;
}

extern "C" void kernel_launch(void* const* d_in, const int* in_sizes, int n_in,
                              void* d_out, int out_size){
    const float* f3  = (const float*)d_in[0];
    const float* f2  = (const float*)d_in[1];
    const float* ftx = (const float*)d_in[2];
    const float* W3  = (const float*)d_in[3];
    const float* b3  = (const float*)d_in[4];
    const float* W2  = (const float*)d_in[5];
    const float* b2  = (const float*)d_in[6];
    const float* Wf  = (const float*)d_in[7];
    const float* bf  = (const float*)d_in[8];
    float* out = (float*)d_out;

    static cudaStream_t s1 = nullptr, s2 = nullptr, s3 = nullptr;
    static cudaEvent_t ev0 = nullptr, ev1 = nullptr, ev2 = nullptr,
                       ev3 = nullptr, evF = nullptr;
    if (!s1){
        cudaStreamCreateWithFlags(&s1, cudaStreamNonBlocking);
        cudaStreamCreateWithFlags(&s2, cudaStreamNonBlocking);
        cudaStreamCreateWithFlags(&s3, cudaStreamNonBlocking);
        cudaEventCreateWithFlags(&ev0, cudaEventDisableTiming);
        cudaEventCreateWithFlags(&ev1, cudaEventDisableTiming);
        cudaEventCreateWithFlags(&ev2, cudaEventDisableTiming);
        cudaEventCreateWithFlags(&ev3, cudaEventDisableTiming);
        cudaEventCreateWithFlags(&evF, cudaEventDisableTiming);
    }

    float* pf3p = nullptr; float* pp2d = nullptr; float* ppt = nullptr;
    cudaGetSymbolAddress((void**)&pf3p, g_f3p);
    cudaGetSymbolAddress((void**)&pp2d, g_p2d);
    cudaGetSymbolAddress((void**)&ppt,  g_ptext);

    // root fork from the caller's stream; all work lives on s1/s2/s3
    cudaEventRecord(ev0, 0);
    cudaStreamWaitEvent(s1, ev0, 0);

    k1_f3p <<<384, 256, 0, s1>>>(f3, W3, b3);
    cudaEventRecord(ev1, s1);

    // text path (depends only on f3p)
    cudaStreamWaitEvent(s2, ev1, 0);
    k5_text<<<1024, 256, 0, s2>>>(ftx);
    k6_comb<<<384, 64, 0, s2>>>();
    cudaEventRecord(ev2, s2);

    // fused GEMM region 0 (x = f3p) — depends only on k1
    cudaStreamWaitEvent(s3, ev1, 0);
    k7_fused<<<576, 256, 0, s3>>>(Wf, pf3p, 0);
    cudaEventRecord(ev3, s3);

    // 2D path on s1
    k2_u   <<<576, 256, 0, s1>>>(W2);
    k_ured <<<24,  256, 0, s1>>>();
    k3a_s2d<<<256, 192, 0, s1>>>(f2);
    k3b_comb<<<32, 256, 0, s1>>>();
    k4_p2d <<<384, 256, 0, s1>>>(W2, b2);
    k7_fused<<<576, 256, 0, s1>>>(Wf, pp2d, PP);      // region 1 (x = pooled_2d)

    // join text -> region 2, then reduce + broadcast (all on s1)
    cudaStreamWaitEvent(s1, ev2, 0);
    k7_fused<<<576, 256, 0, s1>>>(Wf, ppt, 2*PP);     // region 2 (x = pooled_text)
    cudaStreamWaitEvent(s1, ev3, 0);
    k8a_red<<<96,  256, 0, s1>>>(bf);
    k8b_out<<<768, 256, 0, s1>>>(out);

    // join back to the caller's stream
    cudaEventRecord(evF, s1);
    cudaStreamWaitEvent(0, evF, 0);
}

// round 9
// speedup vs baseline: 1.1244x; 1.1244x over previous
#include <cuda_runtime.h>

#define BB   32
#define D3D  256
#define D2D  768
#define DT   3072
#define PP   3072
#define SS   256
#define TT   512
#define SEQ  256
#define XK   (PP*3)     // 9216

#define KS2  96         // k-split for u (p-chunks of 32)
#define SC2  8          // 2D s-splits (chunk 32)
#define TS   16         // text splits per batch (chunk 32)
#define KS7  36         // fused GEMM global splits (k-chunk 256, 12 per region)
#define RS7  132        // ws row stride (floats)
#define RSX  34         // xdup row stride (ulonglong entries)

// ---- scratch (static device memory; no allocation) ----
__device__ float g_f3p[BB*PP];
__device__ float g_upart[KS2*BB*D2D];
__device__ float g_u[BB*D2D];
__device__ float g_m2[BB*SC2];
__device__ float g_z2[BB*SC2];
__device__ float g_v2[BB*SC2*D2D];
__device__ float g_g[BB*D2D];
__device__ float g_p2d[BB*PP];
__device__ float g_mpart[BB*TS];
__device__ float g_zpart[BB*TS];
__device__ float g_vpart[BB*TS*PP];
__device__ float g_ptext[BB*PP];
__device__ float g_fpart[KS7*BB*PP];        // 14.2 MB
__device__ float g_fvec[BB*PP];

__device__ __forceinline__ float warp_sum(float v){
    #pragma unroll
    for (int o = 16; o; o >>= 1) v += __shfl_xor_sync(0xffffffffu, v, o);
    return v;
}

__device__ __forceinline__ void ffma2(unsigned long long& d, unsigned long long a,
                                      unsigned long long b){
    asm("fma.rn.f32x2 %0, %1, %2, %0;" : "+l"(d) : "l"(a), "l"(b));
}

__device__ __forceinline__ unsigned long long dup2(float x){
    unsigned long long r;
    unsigned int u = __float_as_uint(x);
    asm("mov.b64 %0, {%1, %1};" : "=l"(r) : "r"(u));
    return r;
}

__device__ __forceinline__ float dot4(float4 a, float4 b){
    return a.x*b.x + a.y*b.y + a.z*b.z + a.w*b.w;
}

// ---- K1: f3p = feat_3d @ W3d^T + b3d ----
__global__ void k1_f3p(const float* __restrict__ f3, const float* __restrict__ W3,
                       const float* __restrict__ b3){
    int bg = blockIdx.x / 96, pt = blockIdx.x % 96;
    int p0 = pt * 32;
    __shared__ float fs[8*D3D];
    int tid = threadIdx.x, w = tid >> 5, lane = tid & 31;
    #pragma unroll
    for (int e = tid; e < 8*D3D; e += 256) fs[e] = f3[bg*8*D3D + e];
    __syncthreads();
    const float4* fs4 = (const float4*)fs;
    for (int i = 0; i < 4; i++){
        int p = p0 + w*4 + i;
        const float4* row = (const float4*)(W3 + p*D3D);
        float4 a0 = row[lane], a1 = row[lane+32];
        float acc[8];
        #pragma unroll
        for (int bb = 0; bb < 8; bb++){
            float4 c0 = fs4[bb*64 + lane], c1 = fs4[bb*64 + lane + 32];
            acc[bb] = dot4(a0,c0) + dot4(a1,c1);
        }
        #pragma unroll
        for (int bb = 0; bb < 8; bb++){
            float s = warp_sum(acc[bb]);
            if (!lane) g_f3p[(bg*8 + bb)*PP + p] = s + b3[p];
        }
    }
}

// ---- K2: u partials via FFMA2 over bb-pairs (p-chunks of 32) ----
__global__ void __launch_bounds__(256) k2_u(const float* __restrict__ W2){
    int dt = blockIdx.x % 3, ks = blockIdx.x / 3;   // grid 288
    int tid = threadIdx.x;
    int d = dt*256 + tid;
    int pbase = ks * 32;
    __shared__ float fs[32*36];   // fs[pp][bb], row stride 36 (144B, 16B-aligned)
    #pragma unroll
    for (int i = 0; i < 4; i++){
        int e = tid + i*256;
        int bb = e >> 5, pp = e & 31;
        fs[pp*36 + bb] = g_f3p[bb*PP + pbase + pp];
    }
    __syncthreads();
    unsigned long long acc[16];
    #pragma unroll
    for (int j = 0; j < 16; j++) acc[j] = 0ull;
    #pragma unroll 8
    for (int pp = 0; pp < 32; pp++){
        unsigned long long wd = dup2(W2[(size_t)(pbase+pp)*D2D + d]);
        const ulonglong2* fp = (const ulonglong2*)&fs[pp*36];
        #pragma unroll
        for (int j = 0; j < 8; j++){
            ulonglong2 f2 = fp[j];        // bb pairs (4j,4j+1) and (4j+2,4j+3)
            ffma2(acc[2*j],   f2.x, wd);
            ffma2(acc[2*j+1], f2.y, wd);
        }
    }
    #pragma unroll
    for (int j = 0; j < 16; j++){
        float lo = __uint_as_float((unsigned int)(acc[j] & 0xffffffffu));
        float hi = __uint_as_float((unsigned int)(acc[j] >> 32));
        g_upart[(size_t)(ks*BB + 2*j)*D2D + d]     = lo;
        g_upart[(size_t)(ks*BB + 2*j + 1)*D2D + d] = hi;
    }
}

// ---- K2b: reduce partials -> g_u ----
__global__ void k_ured(void){
    int e = blockIdx.x * 256 + threadIdx.x;
    const float4* up = (const float4*)g_upart;
    float4 s = {0,0,0,0};
    #pragma unroll 8
    for (int ks = 0; ks < KS2; ks++){
        float4 v = up[(size_t)ks*(BB*D2D/4) + e];
        s.x += v.x; s.y += v.y; s.z += v.z; s.w += v.w;
    }
    ((float4*)g_u)[e] = s;
}

// ---- K3a: 2D pooling, online softmax, batch-8 rows per sync round ----
__global__ void __launch_bounds__(192) k3a_s2d(const float* __restrict__ f2d){
    __shared__ float red[8][6];
    __shared__ float sbc[8];
    int b = blockIdx.x >> 3, cs = blockIdx.x & 7;
    int s0 = cs * 32;
    int tid = threadIdx.x, w = tid >> 5, lane = tid & 31;
    float4 q = ((const float4*)(g_u + b*D2D))[tid];
    const float4* base = (const float4*)(f2d + ((size_t)(b*SS + s0))*D2D);
    float m = -1e30f, z = 0.f;
    float4 acc = {0,0,0,0};
    for (int tb = 0; tb < 4; tb++){
        float4 r[8];
        #pragma unroll
        for (int j = 0; j < 8; j++) r[j] = base[(tb*8 + j)*192 + tid];
        #pragma unroll
        for (int j = 0; j < 8; j++){
            float p = dot4(r[j], q);
            p = warp_sum(p);
            if (!lane) red[j][w] = p;
        }
        __syncthreads();
        if (tid < 8){
            float s = 0.f;
            #pragma unroll
            for (int i = 0; i < 6; i++) s += red[tid][i];
            sbc[tid] = s;
        }
        __syncthreads();
        #pragma unroll
        for (int j = 0; j < 8; j++){
            float s = sbc[j];
            float mn = fmaxf(m, s);
            float cf = expf(m - mn), wv = expf(s - mn);
            z = z*cf + wv;
            acc.x = acc.x*cf + wv*r[j].x; acc.y = acc.y*cf + wv*r[j].y;
            acc.z = acc.z*cf + wv*r[j].z; acc.w = acc.w*cf + wv*r[j].w;
            m = mn;
        }
        __syncthreads();
    }
    ((float4*)g_v2)[(b*SC2 + cs)*(D2D/4) + tid] = acc;
    if (tid == 0){ g_m2[b*SC2 + cs] = m; g_z2[b*SC2 + cs] = z; }
}

// ---- K3b: combine 2D partials -> g_g ----
__global__ void k3b_comb(void){
    int b = blockIdx.x, tid = threadIdx.x;
    float mv[SC2], co[SC2];
    float m = -1e30f;
    #pragma unroll
    for (int i = 0; i < SC2; i++){ mv[i] = g_m2[b*SC2 + i]; m = fmaxf(m, mv[i]); }
    float zt = 0.f;
    #pragma unroll
    for (int i = 0; i < SC2; i++){ co[i] = expf(mv[i] - m); zt += co[i] * g_z2[b*SC2 + i]; }
    float inv = 1.f / zt;
    if (tid < 192){
        float4 s = {0,0,0,0};
        #pragma unroll
        for (int i = 0; i < SC2; i++){
            float4 v = ((const float4*)g_v2)[(b*SC2 + i)*(D2D/4) + tid];
            s.x += co[i]*v.x; s.y += co[i]*v.y; s.z += co[i]*v.z; s.w += co[i]*v.w;
        }
        s.x *= inv; s.y *= inv; s.z *= inv; s.w *= inv;
        ((float4*)g_g)[b*(D2D/4) + tid] = s;
    }
}

// ---- K4: pooled_2d = g @ W2^T + b2d ----
__global__ void k4_p2d(const float* __restrict__ W2, const float* __restrict__ b2){
    int bg = blockIdx.x / 96, pt = blockIdx.x % 96;
    int p0 = pt * 32;
    __shared__ float gs[8*D2D];
    int tid = threadIdx.x, w = tid >> 5, lane = tid & 31;
    #pragma unroll
    for (int e = tid; e < 8*D2D; e += 256) gs[e] = g_g[bg*8*D2D + e];
    __syncthreads();
    const float4* gs4 = (const float4*)gs;
    for (int i = 0; i < 4; i++){
        int p = p0 + w*4 + i;
        const float4* row = (const float4*)(W2 + p*D2D);
        float4 a[6];
        #pragma unroll
        for (int j = 0; j < 6; j++) a[j] = row[lane + 32*j];
        float acc[8];
        #pragma unroll
        for (int bb = 0; bb < 8; bb++){
            float s = 0.f;
            #pragma unroll
            for (int j = 0; j < 6; j++) s += dot4(a[j], gs4[bb*192 + lane + 32*j]);
            acc[bb] = s;
        }
        #pragma unroll
        for (int bb = 0; bb < 8; bb++){
            float s = warp_sum(acc[bb]);
            if (!lane) g_p2d[(bg*8 + bb)*PP + p] = s + b2[p];
        }
    }
}

// ---- K5: text pooling, online softmax, 32 rows/block, batch-4 per sync round ----
__global__ void __launch_bounds__(256) k5_text(const float* __restrict__ ft){
    __shared__ float red[4][8];
    __shared__ float sbc[4];
    int b = blockIdx.x >> 4, ks = blockIdx.x & 15;
    int t0 = ks * 32;
    int tid = threadIdx.x, w = tid >> 5, lane = tid & 31;
    const float4* qg = (const float4*)(g_f3p + b*PP);
    float4 q0 = qg[tid], q1 = qg[tid+256], q2 = qg[tid+512];
    const float4* base = (const float4*)(ft + ((size_t)(b*TT + t0))*DT);
    float m = -1e30f, z = 0.f;
    float4 a0 = {0,0,0,0}, a1 = {0,0,0,0}, a2 = {0,0,0,0};
    for (int tb = 0; tb < 8; tb++){
        float4 r[4][3];
        #pragma unroll
        for (int j = 0; j < 4; j++){
            const float4* rb = base + (tb*4 + j)*768;
            r[j][0] = rb[tid]; r[j][1] = rb[tid+256]; r[j][2] = rb[tid+512];
        }
        #pragma unroll
        for (int j = 0; j < 4; j++){
            float p = dot4(r[j][0],q0) + dot4(r[j][1],q1) + dot4(r[j][2],q2);
            p = warp_sum(p);
            if (!lane) red[j][w] = p;
        }
        __syncthreads();
        if (tid < 4){
            float s = 0.f;
            #pragma unroll
            for (int i = 0; i < 8; i++) s += red[tid][i];
            sbc[tid] = s;
        }
        __syncthreads();
        #pragma unroll
        for (int j = 0; j < 4; j++){
            float s = sbc[j];
            float mn = fmaxf(m, s);
            float cf = expf(m - mn), wv = expf(s - mn);
            z = z*cf + wv;
            a0.x = a0.x*cf + wv*r[j][0].x; a0.y = a0.y*cf + wv*r[j][0].y;
            a0.z = a0.z*cf + wv*r[j][0].z; a0.w = a0.w*cf + wv*r[j][0].w;
            a1.x = a1.x*cf + wv*r[j][1].x; a1.y = a1.y*cf + wv*r[j][1].y;
            a1.z = a1.z*cf + wv*r[j][1].z; a1.w = a1.w*cf + wv*r[j][1].w;
            a2.x = a2.x*cf + wv*r[j][2].x; a2.y = a2.y*cf + wv*r[j][2].y;
            a2.z = a2.z*cf + wv*r[j][2].z; a2.w = a2.w*cf + wv*r[j][2].w;
            m = mn;
        }
        __syncthreads();
    }
    float4* vp4 = (float4*)g_vpart;
    size_t vb = (size_t)(b*TS + ks) * (PP/4);
    vp4[vb + tid] = a0; vp4[vb + tid + 256] = a1; vp4[vb + tid + 512] = a2;
    if (tid == 0){ g_mpart[b*TS + ks] = m; g_zpart[b*TS + ks] = z; }
}

// ---- K6: combine text partials ----
__global__ void __launch_bounds__(64) k6_comb(void){
    int b = blockIdx.x / 12, ct = blockIdx.x % 12;
    int tid = threadIdx.x;
    __shared__ float ms[TS], zp[TS];
    if (tid < TS){ ms[tid] = g_mpart[b*TS + tid]; zp[tid] = g_zpart[b*TS + tid]; }
    __syncthreads();
    float m = -1e30f;
    #pragma unroll
    for (int i = 0; i < TS; i++) m = fmaxf(m, ms[i]);
    float co[TS];
    float zt = 0.f;
    #pragma unroll
    for (int i = 0; i < TS; i++){ co[i] = expf(ms[i] - m); zt += co[i] * zp[i]; }
    float inv = 1.f / zt;
    int p4 = ct*64 + tid;
    float4 s = {0,0,0,0};
    #pragma unroll 4
    for (int i = 0; i < TS; i++){
        float c = co[i];
        float4 v = ((const float4*)g_vpart)[(size_t)(b*TS + i)*(PP/4) + p4];
        s.x += c*v.x; s.y += c*v.y; s.z += c*v.z; s.w += c*v.w;
    }
    s.x *= inv; s.y *= inv; s.z *= inv; s.w *= inv;
    ((float4*)g_ptext)[b*(PP/4) + p4] = s;
}

// ---- K7: fused GEMM, all 3 k-regions merged, pre-duplicated x in smem ----
// grid 864 = 3 reg x 12 kst x 24 pt; block 128 = 4 bg x 32 pg; tile/thread 8b x 4p
__global__ void __launch_bounds__(128) k7_fused(const float* __restrict__ Wf){
    int region = blockIdx.x / 288;
    int rem = blockIdx.x % 288;
    int pt = rem % 24, kst = rem / 24;     // kst 0..11
    int p0 = pt * 128;
    int koff = kst * 256;                  // within region
    int kglob = region*PP + koff;
    int ks = region*12 + kst;              // global split 0..35
    const float* xsrc = (region == 0) ? g_f3p : (region == 1) ? g_p2d : g_ptext;
    __shared__ float ws[16*RS7];                    // [k][p]
    __shared__ unsigned long long xdup[16*RSX];     // [k][b] duplicated pairs
    int tid = threadIdx.x;
    int bg = tid >> 5, pg = tid & 31;
    int b0 = bg * 8, pp0 = pg * 4;
    unsigned long long acc[8][2];
    #pragma unroll
    for (int i = 0; i < 8; i++){ acc[i][0] = 0ull; acc[i][1] = 0ull; }

    for (int kt = 0; kt < 256; kt += 16){
        // stage ws[k][p]: 16k x 128p
        {
            int c = tid & 3, r0 = tid >> 2;
            #pragma unroll
            for (int i = 0; i < 4; i++){
                int r = r0 + i*32;
                float4 v = *(const float4*)&Wf[(size_t)(p0 + r)*XK + kglob + kt + c*4];
                ws[(c*4+0)*RS7 + r] = v.x;
                ws[(c*4+1)*RS7 + r] = v.y;
                ws[(c*4+2)*RS7 + r] = v.z;
                ws[(c*4+3)*RS7 + r] = v.w;
            }
        }
        // stage xdup[k][b]: duplicated 64-bit pairs
        {
            int bb = tid >> 2, kq = (tid & 3) * 4;
            float4 v = *(const float4*)&xsrc[bb*PP + koff + kt + kq];
            xdup[(kq+0)*RSX + bb] = dup2(v.x);
            xdup[(kq+1)*RSX + bb] = dup2(v.y);
            xdup[(kq+2)*RSX + bb] = dup2(v.z);
            xdup[(kq+3)*RSX + bb] = dup2(v.w);
        }
        __syncthreads();
        #pragma unroll
        for (int k = 0; k < 16; k++){
            const ulonglong2* xp = (const ulonglong2*)&xdup[k*RSX + b0];  // broadcast
            ulonglong2 xa = xp[0], xb = xp[1], xc = xp[2], xe = xp[3];
            ulonglong2 wp = *(const ulonglong2*)&ws[k*RS7 + pp0];
            unsigned long long xd[8] = {xa.x, xa.y, xb.x, xb.y, xc.x, xc.y, xe.x, xe.y};
            #pragma unroll
            for (int i = 0; i < 8; i++){
                ffma2(acc[i][0], xd[i], wp.x);
                ffma2(acc[i][1], xd[i], wp.y);
            }
        }
        __syncthreads();
    }
    #pragma unroll
    for (int i = 0; i < 8; i++){
        int b = b0 + i;
        ulonglong2 o = {acc[i][0], acc[i][1]};
        *(ulonglong2*)&g_fpart[(size_t)(ks*BB + b)*PP + p0 + pp0] = o;
    }
}

// ---- K8a: reduce fused partials + bias -> fvec ----
__global__ void k8a_red(const float* __restrict__ bf){
    int e = blockIdx.x * 256 + threadIdx.x;   // 24576 float4
    int b = e / (PP/4), p4 = e % (PP/4);
    float4 v = ((const float4*)bf)[p4];
    const float4* fp4 = (const float4*)g_fpart;
    #pragma unroll 6
    for (int ks = 0; ks < KS7; ks++){
        float4 a = fp4[(size_t)(ks*BB + b)*(PP/4) + p4];
        v.x += a.x; v.y += a.y; v.z += a.z; v.w += a.w;
    }
    ((float4*)g_fvec)[e] = v;
}

// ---- K8b: broadcast over SEQ ----
__global__ void k8b_out(float* __restrict__ out){
    int bx = blockIdx.x;            // 768 = 32 b x 24 (3 pt x 8 ss)
    int b = bx / 24;
    int rem = bx % 24;
    int pt = rem % 3, ss = rem / 3;
    int tid = threadIdx.x;
    int p4 = pt*256 + tid;
    float4 v = ((const float4*)g_fvec)[b*(PP/4) + p4];
    size_t base = ((size_t)b*SEQ + ss*32)*PP;
    float4* o4 = (float4*)(out + base);
    #pragma unroll 4
    for (int s = 0; s < 32; s++)
        o4[(size_t)s*(PP/4) + p4] = v;
}

extern "C" void kernel_launch(void* const* d_in, const int* in_sizes, int n_in,
                              void* d_out, int out_size){
    const float* f3  = (const float*)d_in[0];
    const float* f2  = (const float*)d_in[1];
    const float* ftx = (const float*)d_in[2];
    const float* W3  = (const float*)d_in[3];
    const float* b3  = (const float*)d_in[4];
    const float* W2  = (const float*)d_in[5];
    const float* b2  = (const float*)d_in[6];
    const float* Wf  = (const float*)d_in[7];
    const float* bf  = (const float*)d_in[8];
    float* out = (float*)d_out;

    static cudaStream_t s1 = nullptr, s2 = nullptr;
    static cudaEvent_t ev0 = nullptr, ev1 = nullptr, ev2 = nullptr, evF = nullptr;
    if (!s1){
        cudaStreamCreateWithFlags(&s1, cudaStreamNonBlocking);
        cudaStreamCreateWithFlags(&s2, cudaStreamNonBlocking);
        cudaEventCreateWithFlags(&ev0, cudaEventDisableTiming);
        cudaEventCreateWithFlags(&ev1, cudaEventDisableTiming);
        cudaEventCreateWithFlags(&ev2, cudaEventDisableTiming);
        cudaEventCreateWithFlags(&evF, cudaEventDisableTiming);
    }

    // root fork from caller's stream
    cudaEventRecord(ev0, 0);
    cudaStreamWaitEvent(s1, ev0, 0);

    k1_f3p <<<384, 256, 0, s1>>>(f3, W3, b3);
    cudaEventRecord(ev1, s1);

    // text path (depends only on f3p)
    cudaStreamWaitEvent(s2, ev1, 0);
    k5_text<<<512, 256, 0, s2>>>(ftx);
    k6_comb<<<384, 64, 0, s2>>>();
    cudaEventRecord(ev2, s2);

    // 2D path on s1
    k2_u   <<<288, 256, 0, s1>>>(W2);
    k_ured <<<24,  256, 0, s1>>>();
    k3a_s2d<<<256, 192, 0, s1>>>(f2);
    k3b_comb<<<32, 256, 0, s1>>>();
    k4_p2d <<<384, 256, 0, s1>>>(W2, b2);

    // join text -> merged fused GEMM -> reduce -> broadcast
    cudaStreamWaitEvent(s1, ev2, 0);
    k7_fused<<<864, 128, 0, s1>>>(Wf);
    k8a_red<<<96,  256, 0, s1>>>(bf);
    k8b_out<<<768, 256, 0, s1>>>(out);

    // join back to caller's stream
    cudaEventRecord(evF, s1);
    cudaStreamWaitEvent(0, evF, 0);
}

// round 10
// speedup vs baseline: 1.2187x; 1.0839x over previous
#include <cuda_runtime.h>

#define BB   32
#define D3D  256
#define D2D  768
#define DT   3072
#define PP   3072
#define SS   256
#define TT   512
#define SEQ  256
#define XK   (PP*3)     // 9216

#define KS2  96         // k-split for u (p-chunks of 32)
#define SC2  16         // 2D s-splits (chunk 16)
#define TS   16         // text splits per batch (chunk 32)
#define KS7  48         // fused GEMM global splits (k-chunk 192, 16 per region)
#define RS7  260        // ws row stride (floats) for 256-wide p tile
#define RSX  34         // xdup row stride (ulonglong entries)

// ---- scratch (static device memory; no allocation) ----
__device__ float g_f3p[BB*PP];
__device__ float g_upart[KS2*BB*D2D];
__device__ float g_u[BB*D2D];
__device__ float g_m2[BB*SC2];
__device__ float g_z2[BB*SC2];
__device__ float g_v2[BB*SC2*D2D];
__device__ float g_g[BB*D2D];
__device__ float g_p2d[BB*PP];
__device__ float g_mpart[BB*TS];
__device__ float g_zpart[BB*TS];
__device__ float g_vpart[BB*TS*PP];
__device__ float g_ptext[BB*PP];
__device__ float g_fpart[KS7*BB*PP];        // 18.9 MB
__device__ float g_fvec[BB*PP];

__device__ __forceinline__ float warp_sum(float v){
    #pragma unroll
    for (int o = 16; o; o >>= 1) v += __shfl_xor_sync(0xffffffffu, v, o);
    return v;
}

__device__ __forceinline__ void ffma2(unsigned long long& d, unsigned long long a,
                                      unsigned long long b){
    asm("fma.rn.f32x2 %0, %1, %2, %0;" : "+l"(d) : "l"(a), "l"(b));
}

__device__ __forceinline__ unsigned long long dup2(float x){
    unsigned long long r;
    unsigned int u = __float_as_uint(x);
    asm("mov.b64 %0, {%1, %1};" : "=l"(r) : "r"(u));
    return r;
}

__device__ __forceinline__ float dot4(float4 a, float4 b){
    return a.x*b.x + a.y*b.y + a.z*b.z + a.w*b.w;
}

// ---- K1: f3p = feat_3d @ W3d^T + b3d ----
__global__ void k1_f3p(const float* __restrict__ f3, const float* __restrict__ W3,
                       const float* __restrict__ b3){
    int bg = blockIdx.x / 96, pt = blockIdx.x % 96;
    int p0 = pt * 32;
    __shared__ float fs[8*D3D];
    int tid = threadIdx.x, w = tid >> 5, lane = tid & 31;
    #pragma unroll
    for (int e = tid; e < 8*D3D; e += 256) fs[e] = f3[bg*8*D3D + e];
    __syncthreads();
    const float4* fs4 = (const float4*)fs;
    for (int i = 0; i < 4; i++){
        int p = p0 + w*4 + i;
        const float4* row = (const float4*)(W3 + p*D3D);
        float4 a0 = row[lane], a1 = row[lane+32];
        float acc[8];
        #pragma unroll
        for (int bb = 0; bb < 8; bb++){
            float4 c0 = fs4[bb*64 + lane], c1 = fs4[bb*64 + lane + 32];
            acc[bb] = dot4(a0,c0) + dot4(a1,c1);
        }
        #pragma unroll
        for (int bb = 0; bb < 8; bb++){
            float s = warp_sum(acc[bb]);
            if (!lane) g_f3p[(bg*8 + bb)*PP + p] = s + b3[p];
        }
    }
}

// ---- K2: u partials — float4 W2 loads, natural d-pair FFMA2 ----
// grid 96 (p-chunk 32); block 384 = 2 bgroup x 192 dgroup
__global__ void __launch_bounds__(384) k2_u(const float* __restrict__ W2){
    int ks = blockIdx.x;
    int pbase = ks * 32;
    int tid = threadIdx.x;
    int bg = tid / 192, dg = tid % 192;
    int d4 = dg * 4, b0 = bg * 16;
    __shared__ float fs[32*33];   // fs[pp][bb]
    for (int e = tid; e < 32*32; e += 384){
        int pp = e >> 5, bb = e & 31;
        fs[pp*33 + bb] = g_f3p[bb*PP + pbase + pp];
    }
    __syncthreads();
    unsigned long long acc[16][2];
    #pragma unroll
    for (int b = 0; b < 16; b++){ acc[b][0] = 0ull; acc[b][1] = 0ull; }
    #pragma unroll 4
    for (int pp = 0; pp < 32; pp++){
        float4 wv = *(const float4*)&W2[(size_t)(pbase+pp)*D2D + d4];
        ulonglong2 wp = *reinterpret_cast<const ulonglong2*>(&wv);
        #pragma unroll
        for (int b = 0; b < 16; b++){
            unsigned long long xd = dup2(fs[pp*33 + b0 + b]);
            ffma2(acc[b][0], xd, wp.x);
            ffma2(acc[b][1], xd, wp.y);
        }
    }
    #pragma unroll
    for (int b = 0; b < 16; b++){
        ulonglong2 o = {acc[b][0], acc[b][1]};
        *(ulonglong2*)&g_upart[(size_t)(ks*BB + b0 + b)*D2D + d4] = o;
    }
}

// ---- K2b: reduce partials -> g_u (4-way ks split + smem combine) ----
__global__ void k_ured(void){   // grid 96 x 256
    int tid = threadIdx.x;
    int gid = blockIdx.x * 256 + tid;   // 24576 = 6144 f4 x 4 parts
    int e = gid >> 2;
    int part = gid & 3;
    const float4* up = (const float4*)g_upart;
    float4 s = {0,0,0,0};
    #pragma unroll 8
    for (int ks = part*24; ks < part*24 + 24; ks++){
        float4 v = up[(size_t)ks*(BB*D2D/4) + e];
        s.x += v.x; s.y += v.y; s.z += v.z; s.w += v.w;
    }
    __shared__ float4 sm[256];
    sm[tid] = s;
    __syncthreads();
    if (part == 0){
        float4 a = sm[tid+1], b = sm[tid+2], c = sm[tid+3];
        s.x += a.x + b.x + c.x; s.y += a.y + b.y + c.y;
        s.z += a.z + b.z + c.z; s.w += a.w + b.w + c.w;
        ((float4*)g_u)[e] = s;
    }
}

// ---- K3a: 2D pooling, online softmax, 16 rows/block (2 rounds of 8) ----
__global__ void __launch_bounds__(192) k3a_s2d(const float* __restrict__ f2d){
    __shared__ float red[8][6];
    __shared__ float sbc[8];
    int b = blockIdx.x >> 4, cs = blockIdx.x & 15;
    int s0 = cs * 16;
    int tid = threadIdx.x, w = tid >> 5, lane = tid & 31;
    float4 q = ((const float4*)(g_u + b*D2D))[tid];
    const float4* base = (const float4*)(f2d + ((size_t)(b*SS + s0))*D2D);
    float m = -1e30f, z = 0.f;
    float4 acc = {0,0,0,0};
    for (int tb = 0; tb < 2; tb++){
        float4 r[8];
        #pragma unroll
        for (int j = 0; j < 8; j++) r[j] = base[(tb*8 + j)*192 + tid];
        #pragma unroll
        for (int j = 0; j < 8; j++){
            float p = dot4(r[j], q);
            p = warp_sum(p);
            if (!lane) red[j][w] = p;
        }
        __syncthreads();
        if (tid < 8){
            float s = 0.f;
            #pragma unroll
            for (int i = 0; i < 6; i++) s += red[tid][i];
            sbc[tid] = s;
        }
        __syncthreads();
        #pragma unroll
        for (int j = 0; j < 8; j++){
            float s = sbc[j];
            float mn = fmaxf(m, s);
            float cf = expf(m - mn), wv = expf(s - mn);
            z = z*cf + wv;
            acc.x = acc.x*cf + wv*r[j].x; acc.y = acc.y*cf + wv*r[j].y;
            acc.z = acc.z*cf + wv*r[j].z; acc.w = acc.w*cf + wv*r[j].w;
            m = mn;
        }
        __syncthreads();
    }
    ((float4*)g_v2)[(b*SC2 + cs)*(D2D/4) + tid] = acc;
    if (tid == 0){ g_m2[b*SC2 + cs] = m; g_z2[b*SC2 + cs] = z; }
}

// ---- K3b: combine 2D partials -> g_g ----
__global__ void k3b_comb(void){
    int b = blockIdx.x, tid = threadIdx.x;
    float mv[SC2], co[SC2];
    float m = -1e30f;
    #pragma unroll
    for (int i = 0; i < SC2; i++){ mv[i] = g_m2[b*SC2 + i]; m = fmaxf(m, mv[i]); }
    float zt = 0.f;
    #pragma unroll
    for (int i = 0; i < SC2; i++){ co[i] = expf(mv[i] - m); zt += co[i] * g_z2[b*SC2 + i]; }
    float inv = 1.f / zt;
    if (tid < 192){
        float4 s = {0,0,0,0};
        #pragma unroll
        for (int i = 0; i < SC2; i++){
            float4 v = ((const float4*)g_v2)[(b*SC2 + i)*(D2D/4) + tid];
            s.x += co[i]*v.x; s.y += co[i]*v.y; s.z += co[i]*v.z; s.w += co[i]*v.w;
        }
        s.x *= inv; s.y *= inv; s.z *= inv; s.w *= inv;
        ((float4*)g_g)[b*(D2D/4) + tid] = s;
    }
}

// ---- K4: pooled_2d = g @ W2^T + b2d ----
__global__ void k4_p2d(const float* __restrict__ W2, const float* __restrict__ b2){
    int bg = blockIdx.x / 96, pt = blockIdx.x % 96;
    int p0 = pt * 32;
    __shared__ float gs[8*D2D];
    int tid = threadIdx.x, w = tid >> 5, lane = tid & 31;
    #pragma unroll
    for (int e = tid; e < 8*D2D; e += 256) gs[e] = g_g[bg*8*D2D + e];
    __syncthreads();
    const float4* gs4 = (const float4*)gs;
    for (int i = 0; i < 4; i++){
        int p = p0 + w*4 + i;
        const float4* row = (const float4*)(W2 + p*D2D);
        float4 a[6];
        #pragma unroll
        for (int j = 0; j < 6; j++) a[j] = row[lane + 32*j];
        float acc[8];
        #pragma unroll
        for (int bb = 0; bb < 8; bb++){
            float s = 0.f;
            #pragma unroll
            for (int j = 0; j < 6; j++) s += dot4(a[j], gs4[bb*192 + lane + 32*j]);
            acc[bb] = s;
        }
        #pragma unroll
        for (int bb = 0; bb < 8; bb++){
            float s = warp_sum(acc[bb]);
            if (!lane) g_p2d[(bg*8 + bb)*PP + p] = s + b2[p];
        }
    }
}

// ---- K5: text pooling, online softmax, 32 rows/block, batch-4 per sync round ----
__global__ void __launch_bounds__(256) k5_text(const float* __restrict__ ft){
    __shared__ float red[4][8];
    __shared__ float sbc[4];
    int b = blockIdx.x >> 4, ks = blockIdx.x & 15;
    int t0 = ks * 32;
    int tid = threadIdx.x, w = tid >> 5, lane = tid & 31;
    const float4* qg = (const float4*)(g_f3p + b*PP);
    float4 q0 = qg[tid], q1 = qg[tid+256], q2 = qg[tid+512];
    const float4* base = (const float4*)(ft + ((size_t)(b*TT + t0))*DT);
    float m = -1e30f, z = 0.f;
    float4 a0 = {0,0,0,0}, a1 = {0,0,0,0}, a2 = {0,0,0,0};
    for (int tb = 0; tb < 8; tb++){
        float4 r[4][3];
        #pragma unroll
        for (int j = 0; j < 4; j++){
            const float4* rb = base + (tb*4 + j)*768;
            r[j][0] = rb[tid]; r[j][1] = rb[tid+256]; r[j][2] = rb[tid+512];
        }
        #pragma unroll
        for (int j = 0; j < 4; j++){
            float p = dot4(r[j][0],q0) + dot4(r[j][1],q1) + dot4(r[j][2],q2);
            p = warp_sum(p);
            if (!lane) red[j][w] = p;
        }
        __syncthreads();
        if (tid < 4){
            float s = 0.f;
            #pragma unroll
            for (int i = 0; i < 8; i++) s += red[tid][i];
            sbc[tid] = s;
        }
        __syncthreads();
        #pragma unroll
        for (int j = 0; j < 4; j++){
            float s = sbc[j];
            float mn = fmaxf(m, s);
            float cf = expf(m - mn), wv = expf(s - mn);
            z = z*cf + wv;
            a0.x = a0.x*cf + wv*r[j][0].x; a0.y = a0.y*cf + wv*r[j][0].y;
            a0.z = a0.z*cf + wv*r[j][0].z; a0.w = a0.w*cf + wv*r[j][0].w;
            a1.x = a1.x*cf + wv*r[j][1].x; a1.y = a1.y*cf + wv*r[j][1].y;
            a1.z = a1.z*cf + wv*r[j][1].z; a1.w = a1.w*cf + wv*r[j][1].w;
            a2.x = a2.x*cf + wv*r[j][2].x; a2.y = a2.y*cf + wv*r[j][2].y;
            a2.z = a2.z*cf + wv*r[j][2].z; a2.w = a2.w*cf + wv*r[j][2].w;
            m = mn;
        }
        __syncthreads();
    }
    float4* vp4 = (float4*)g_vpart;
    size_t vb = (size_t)(b*TS + ks) * (PP/4);
    vp4[vb + tid] = a0; vp4[vb + tid + 256] = a1; vp4[vb + tid + 512] = a2;
    if (tid == 0){ g_mpart[b*TS + ks] = m; g_zpart[b*TS + ks] = z; }
}

// ---- K6: combine text partials ----
__global__ void __launch_bounds__(64) k6_comb(void){
    int b = blockIdx.x / 12, ct = blockIdx.x % 12;
    int tid = threadIdx.x;
    __shared__ float ms[TS], zp[TS];
    if (tid < TS){ ms[tid] = g_mpart[b*TS + tid]; zp[tid] = g_zpart[b*TS + tid]; }
    __syncthreads();
    float m = -1e30f;
    #pragma unroll
    for (int i = 0; i < TS; i++) m = fmaxf(m, ms[i]);
    float co[TS];
    float zt = 0.f;
    #pragma unroll
    for (int i = 0; i < TS; i++){ co[i] = expf(ms[i] - m); zt += co[i] * zp[i]; }
    float inv = 1.f / zt;
    int p4 = ct*64 + tid;
    float4 s = {0,0,0,0};
    #pragma unroll 4
    for (int i = 0; i < TS; i++){
        float c = co[i];
        float4 v = ((const float4*)g_vpart)[(size_t)(b*TS + i)*(PP/4) + p4];
        s.x += c*v.x; s.y += c*v.y; s.z += c*v.z; s.w += c*v.w;
    }
    s.x *= inv; s.y *= inv; s.z *= inv; s.w *= inv;
    ((float4*)g_ptext)[b*(PP/4) + p4] = s;
}

// ---- K7: fused GEMM, 3 regions merged, 8b x 8p (two conflict-free quads) ----
// grid 576 = 3 reg x 16 kst x 12 pt; block 128 = 4 bg x 32 pg
__global__ void __launch_bounds__(128) k7_fused(const float* __restrict__ Wf){
    int region = blockIdx.x / 192;
    int rem = blockIdx.x % 192;
    int pt = rem % 12, kst = rem / 12;     // kst 0..15
    int p0 = pt * 256;
    int koff = kst * 192;
    int kglob = region*PP + koff;
    int ks = region*16 + kst;
    const float* xsrc = (region == 0) ? g_f3p : (region == 1) ? g_p2d : g_ptext;
    __shared__ float ws[16*RS7];                    // [k][p] 256-wide
    __shared__ unsigned long long xdup[16*RSX];     // [k][b] duplicated pairs
    int tid = threadIdx.x;
    int bg = tid >> 5, pg = tid & 31;
    int b0 = bg * 8, pq = pg * 4;
    unsigned long long acc[8][4];
    #pragma unroll
    for (int i = 0; i < 8; i++)
        #pragma unroll
        for (int j = 0; j < 4; j++) acc[i][j] = 0ull;

    for (int kt = 0; kt < 192; kt += 16){
        // stage ws[k][p]: 16k x 256p
        {
            int c = tid & 3, r0 = tid >> 2;
            #pragma unroll
            for (int i = 0; i < 8; i++){
                int r = r0 + i*32;
                float4 v = *(const float4*)&Wf[(size_t)(p0 + r)*XK + kglob + kt + c*4];
                ws[(c*4+0)*RS7 + r] = v.x;
                ws[(c*4+1)*RS7 + r] = v.y;
                ws[(c*4+2)*RS7 + r] = v.z;
                ws[(c*4+3)*RS7 + r] = v.w;
            }
        }
        // stage xdup[k][b]
        {
            int bb = tid >> 2, kq = (tid & 3) * 4;
            float4 v = *(const float4*)&xsrc[bb*PP + koff + kt + kq];
            xdup[(kq+0)*RSX + bb] = dup2(v.x);
            xdup[(kq+1)*RSX + bb] = dup2(v.y);
            xdup[(kq+2)*RSX + bb] = dup2(v.z);
            xdup[(kq+3)*RSX + bb] = dup2(v.w);
        }
        __syncthreads();
        #pragma unroll
        for (int k = 0; k < 16; k++){
            const ulonglong2* xp = (const ulonglong2*)&xdup[k*RSX + b0];  // broadcast
            ulonglong2 x0 = xp[0], x1 = xp[1], x2 = xp[2], x3 = xp[3];
            ulonglong2 wa = *(const ulonglong2*)&ws[k*RS7 + pq];          // CF 16B stride
            ulonglong2 wb = *(const ulonglong2*)&ws[k*RS7 + 128 + pq];    // CF 16B stride
            unsigned long long xd[8] = {x0.x,x0.y,x1.x,x1.y,x2.x,x2.y,x3.x,x3.y};
            #pragma unroll
            for (int i = 0; i < 8; i++){
                ffma2(acc[i][0], xd[i], wa.x);
                ffma2(acc[i][1], xd[i], wa.y);
                ffma2(acc[i][2], xd[i], wb.x);
                ffma2(acc[i][3], xd[i], wb.y);
            }
        }
        __syncthreads();
    }
    #pragma unroll
    for (int i = 0; i < 8; i++){
        int b = b0 + i;
        size_t base = (size_t)(ks*BB + b)*PP + p0;
        ulonglong2 oa = {acc[i][0], acc[i][1]};
        ulonglong2 ob = {acc[i][2], acc[i][3]};
        *(ulonglong2*)&g_fpart[base + pq] = oa;
        *(ulonglong2*)&g_fpart[base + 128 + pq] = ob;
    }
}

// ---- K8a: reduce fused partials + bias -> fvec ----
__global__ void k8a_red(const float* __restrict__ bf){
    int e = blockIdx.x * 256 + threadIdx.x;   // 24576 float4
    int b = e / (PP/4), p4 = e % (PP/4);
    float4 v = ((const float4*)bf)[p4];
    const float4* fp4 = (const float4*)g_fpart;
    #pragma unroll 8
    for (int ks = 0; ks < KS7; ks++){
        float4 a = fp4[(size_t)(ks*BB + b)*(PP/4) + p4];
        v.x += a.x; v.y += a.y; v.z += a.z; v.w += a.w;
    }
    ((float4*)g_fvec)[e] = v;
}

// ---- K8b: broadcast over SEQ ----
__global__ void k8b_out(float* __restrict__ out){
    int bx = blockIdx.x;            // 768 = 32 b x 24 (3 pt x 8 ss)
    int b = bx / 24;
    int rem = bx % 24;
    int pt = rem % 3, ss = rem / 3;
    int tid = threadIdx.x;
    int p4 = pt*256 + tid;
    float4 v = ((const float4*)g_fvec)[b*(PP/4) + p4];
    size_t base = ((size_t)b*SEQ + ss*32)*PP;
    float4* o4 = (float4*)(out + base);
    #pragma unroll 4
    for (int s = 0; s < 32; s++)
        o4[(size_t)s*(PP/4) + p4] = v;
}

extern "C" void kernel_launch(void* const* d_in, const int* in_sizes, int n_in,
                              void* d_out, int out_size){
    const float* f3  = (const float*)d_in[0];
    const float* f2  = (const float*)d_in[1];
    const float* ftx = (const float*)d_in[2];
    const float* W3  = (const float*)d_in[3];
    const float* b3  = (const float*)d_in[4];
    const float* W2  = (const float*)d_in[5];
    const float* b2  = (const float*)d_in[6];
    const float* Wf  = (const float*)d_in[7];
    const float* bf  = (const float*)d_in[8];
    float* out = (float*)d_out;

    static cudaStream_t s1 = nullptr, s2 = nullptr;
    static cudaEvent_t ev0 = nullptr, ev1 = nullptr, ev2 = nullptr, evF = nullptr;
    if (!s1){
        cudaStreamCreateWithFlags(&s1, cudaStreamNonBlocking);
        cudaStreamCreateWithFlags(&s2, cudaStreamNonBlocking);
        cudaEventCreateWithFlags(&ev0, cudaEventDisableTiming);
        cudaEventCreateWithFlags(&ev1, cudaEventDisableTiming);
        cudaEventCreateWithFlags(&ev2, cudaEventDisableTiming);
        cudaEventCreateWithFlags(&evF, cudaEventDisableTiming);
    }

    // root fork from caller's stream
    cudaEventRecord(ev0, 0);
    cudaStreamWaitEvent(s1, ev0, 0);

    k1_f3p <<<384, 256, 0, s1>>>(f3, W3, b3);
    cudaEventRecord(ev1, s1);

    // text path (depends only on f3p)
    cudaStreamWaitEvent(s2, ev1, 0);
    k5_text<<<512, 256, 0, s2>>>(ftx);
    k6_comb<<<384, 64, 0, s2>>>();
    cudaEventRecord(ev2, s2);

    // 2D path on s1
    k2_u   <<<96,  384, 0, s1>>>(W2);
    k_ured <<<96,  256, 0, s1>>>();
    k3a_s2d<<<512, 192, 0, s1>>>(f2);
    k3b_comb<<<32, 256, 0, s1>>>();
    k4_p2d <<<384, 256, 0, s1>>>(W2, b2);

    // join text -> merged fused GEMM -> reduce -> broadcast
    cudaStreamWaitEvent(s1, ev2, 0);
    k7_fused<<<576, 128, 0, s1>>>(Wf);
    k8a_red<<<96,  256, 0, s1>>>(bf);
    k8b_out<<<768, 256, 0, s1>>>(out);

    // join back to caller's stream
    cudaEventRecord(evF, s1);
    cudaStreamWaitEvent(0, evF, 0);
}